// round 6
// baseline (speedup 1.0000x reference)
#include <cuda_runtime.h>
#include <cstdint>
#include <cstddef>

#define BDIM 64
#define TDIM 512
#define DDIM 512
#define HDIM 1024
#define ODIM 512
#define G3   3072
#define MROWS 32768            // B*T
#define RCTA 64                // recurrence CTAs (single wave)
#define RJ   16                // hidden units per recurrence CTA

// Scratch (device globals are the sanctioned no-alloc workaround)
__device__ float g_xall[(size_t)MROWS * G3];        // x projection, 402 MB
__device__ unsigned g_hfrag[2][BDIM * HDIM];        // h ping-pong (tf32, A-fragment-major)
__device__ unsigned g_count;                        // barrier arrivals (RMW line)
__device__ unsigned g_flag;                         // barrier epoch flag (read-only line)

__device__ __forceinline__ unsigned f2tf32(float x) {
    unsigned r;
    asm("cvt.rna.tf32.f32 %0, %1;" : "=r"(r) : "f"(x));
    return r;
}

__device__ __forceinline__ void mma_tf32_k8(float* d,
    unsigned a0, unsigned a1, unsigned a2, unsigned a3,
    unsigned b0, unsigned b1)
{
    asm volatile(
        "mma.sync.aligned.m16n8k8.row.col.f32.tf32.tf32.f32 "
        "{%0,%1,%2,%3}, {%4,%5,%6,%7}, {%8,%9}, {%0,%1,%2,%3};\n"
        : "+f"(d[0]), "+f"(d[1]), "+f"(d[2]), "+f"(d[3])
        : "r"(a0), "r"(a1), "r"(a2), "r"(a3), "r"(b0), "r"(b1));
}

__device__ __forceinline__ float sigmoidf_(float x) {
    return 1.0f / (1.0f + __expf(-x));
}
__device__ __forceinline__ float tanhf_(float x) {
    x = fminf(fmaxf(x, -15.0f), 15.0f);
    float e = __expf(-2.0f * x);
    return (1.0f - e) / (1.0f + e);
}

// ---------------------------------------------------------------------------
// Generic NT GEMM: C[M,N] = A[M,K](rm) * B[N,K](rm)^T + bias[N]
// Tiles: BM=128, BN=128, BK=32; 256 threads; warp grid 4(m) x 2(n).
// tf32 m16n8k8 MMA; smem k-major, pad 132.
// ---------------------------------------------------------------------------
__global__ __launch_bounds__(256) void gemm_nt_kernel(
    const float* __restrict__ A, const float* __restrict__ B,
    const float* __restrict__ bias, float* __restrict__ C,
    int N, int K)
{
    __shared__ unsigned As[32][132];
    __shared__ unsigned Bs[32][132];
    const int tid  = threadIdx.x;
    const int lane = tid & 31;
    const int warp = tid >> 5;
    const int wm = warp & 3;
    const int wn = warp >> 2;
    const int g = lane >> 2;
    const int c = lane & 3;
    const int bm = blockIdx.y, bn = blockIdx.x;
    const float* Ab = A + (size_t)bm * 128 * K;
    const float* Bb = B + (size_t)bn * 128 * K;

    float acc[2][8][4];
#pragma unroll
    for (int i = 0; i < 2; i++)
#pragma unroll
        for (int j = 0; j < 8; j++)
#pragma unroll
            for (int e = 0; e < 4; e++) acc[i][j][e] = 0.0f;

    for (int k0 = 0; k0 < K; k0 += 32) {
        __syncthreads();
#pragma unroll
        for (int p = 0; p < 4; p++) {
            int flat = p * 256 + tid;
            int row = flat >> 3;
            int ks = (flat & 7) * 4;
            float4 va = *(const float4*)(Ab + (size_t)row * K + k0 + ks);
            As[ks + 0][row] = f2tf32(va.x);
            As[ks + 1][row] = f2tf32(va.y);
            As[ks + 2][row] = f2tf32(va.z);
            As[ks + 3][row] = f2tf32(va.w);
            float4 vb = *(const float4*)(Bb + (size_t)row * K + k0 + ks);
            Bs[ks + 0][row] = f2tf32(vb.x);
            Bs[ks + 1][row] = f2tf32(vb.y);
            Bs[ks + 2][row] = f2tf32(vb.z);
            Bs[ks + 3][row] = f2tf32(vb.w);
        }
        __syncthreads();
#pragma unroll
        for (int ks = 0; ks < 32; ks += 8) {
            unsigned a[2][4], b[8][2];
#pragma unroll
            for (int mt = 0; mt < 2; mt++) {
                int mb = wm * 32 + mt * 16;
                a[mt][0] = As[ks + c][mb + g];
                a[mt][1] = As[ks + c][mb + g + 8];
                a[mt][2] = As[ks + c + 4][mb + g];
                a[mt][3] = As[ks + c + 4][mb + g + 8];
            }
#pragma unroll
            for (int nt = 0; nt < 8; nt++) {
                int col = wn * 64 + nt * 8 + g;
                b[nt][0] = Bs[ks + c][col];
                b[nt][1] = Bs[ks + c + 4][col];
            }
#pragma unroll
            for (int mt = 0; mt < 2; mt++)
#pragma unroll
                for (int nt = 0; nt < 8; nt++)
                    mma_tf32_k8(acc[mt][nt], a[mt][0], a[mt][1], a[mt][2], a[mt][3],
                                b[nt][0], b[nt][1]);
        }
    }

#pragma unroll
    for (int mt = 0; mt < 2; mt++) {
        int row = bm * 128 + wm * 32 + mt * 16 + g;
#pragma unroll
        for (int nt = 0; nt < 8; nt++) {
            int col = bn * 128 + wn * 64 + nt * 8 + 2 * c;
            float b0 = bias[col], b1 = bias[col + 1];
            C[(size_t)row * N + col]           = acc[mt][nt][0] + b0;
            C[(size_t)row * N + col + 1]       = acc[mt][nt][1] + b1;
            C[(size_t)(row + 8) * N + col]     = acc[mt][nt][2] + b0;
            C[(size_t)(row + 8) * N + col + 1] = acc[mt][nt][3] + b1;
        }
    }
}

// ---------------------------------------------------------------------------
// Persistent GRU recurrence. 64 CTAs (single wave), 512 threads each.
// CTA owns RJ=16 hidden units; warps: mt=warp&3 (16 batch rows), kh=warp>>2
// (K quarter). Wh SMEM-resident in B-frag order; h in GMEM in A-frag order.
// h_prev lives in epilogue-warp registers (CTA re-reads exactly what it wrote).
// Barrier: acq_rel RMW arrivals on g_count + release flag broadcast on g_flag;
// hiddens STG and next-x prefetch issued AFTER arrive (hidden behind the wait).
// ---------------------------------------------------------------------------
extern __shared__ unsigned rec_smem[];   // Whs[49152] + red[6400 floats]

__device__ __forceinline__ void load_x(int t, int b0r, int b1r, int j0, int c,
                                       float2 xv[3][2][2])
{
#pragma unroll
    for (int gi = 0; gi < 3; gi++)
#pragma unroll
        for (int jh = 0; jh < 2; jh++) {
            int jj = j0 + jh * 8 + 2 * c;
            xv[gi][jh][0] = *(const float2*)&g_xall[((size_t)b0r * TDIM + t) * G3 + gi * HDIM + jj];
            xv[gi][jh][1] = *(const float2*)&g_xall[((size_t)b1r * TDIM + t) * G3 + gi * HDIM + jj];
        }
}

__global__ __launch_bounds__(512, 1) void gru_rec_kernel(
    const float* __restrict__ Wh, const float* __restrict__ bh,
    float* __restrict__ hiddens)
{
    unsigned* Whs = rec_smem;                       // [kb128][gate3][jh2][lane32][2]
    float* red = (float*)(rec_smem + 49152);        // [buf2][mt4*lane32][25]
    const int tid  = threadIdx.x;
    const int lane = tid & 31;
    const int warp = tid >> 5;
    const int mt = warp & 3;        // batch quarter (16 rows)
    const int kh = warp >> 2;       // K quarter (0..3)
    const int g = lane >> 2, c = lane & 3;
    const int j0 = blockIdx.x * RJ;

    // Load Wh slice -> SMEM in B-fragment order (tf32), once.
    for (int flat = tid; flat < 128 * 6 * 32; flat += 512) {
        int kb = flat / 192, rem = flat % 192;
        int gi = rem >> 6;            // gate
        int jh = (rem >> 5) & 1;      // j-half
        int ln = rem & 31;
        int gg = ln >> 2, cc = ln & 3;
        const float* wp = Wh + (size_t)(gi * HDIM + j0 + jh * 8 + gg) * HDIM + kb * 8 + cc;
        Whs[flat * 2 + 0] = f2tf32(wp[0]);
        Whs[flat * 2 + 1] = f2tf32(wp[4]);
    }

    const int b0r = mt * 16 + g, b1r = b0r + 8;
    float bhv[3][2][2];               // [gate][jh][part]
#pragma unroll
    for (int gi = 0; gi < 3; gi++)
#pragma unroll
        for (int jh = 0; jh < 2; jh++) {
            int jj = j0 + jh * 8 + 2 * c;
            bhv[gi][jh][0] = bh[gi * HDIM + jj];
            bhv[gi][jh][1] = bh[gi * HDIM + jj + 1];
        }

    // Epilogue-warp persistent state: x_t prefetch and h_prev registers.
    float2 xv[3][2][2];
    float hpr[2][4];
#pragma unroll
    for (int jh = 0; jh < 2; jh++)
#pragma unroll
        for (int e = 0; e < 4; e++) hpr[jh][e] = 0.0f;
    if (kh == 0) load_x(0, b0r, b1r, j0, c, xv);

    __syncthreads();

    for (int t = 0; t < TDIM; t++) {
        const int pp = t & 1;

        float acc[3][2][4];
#pragma unroll
        for (int gi = 0; gi < 3; gi++)
#pragma unroll
            for (int jh = 0; jh < 2; jh++)
#pragma unroll
                for (int e = 0; e < 4; e++) acc[gi][jh][e] = 0.0f;

        // A-frag stream: base for this warp's (kh, mt); per-kb stride 512 u32.
        const unsigned* hfp = g_hfrag[pp] + (((kh * 32 * 4 + mt) * 32 + lane) << 2);
        uint4 a0 = __ldcg((const uint4*)hfp);
        uint4 a1 = __ldcg((const uint4*)(hfp + 512));

#pragma unroll 4
        for (int it = 0; it < 32; it++) {
            uint4 an = a1;
            if (it < 30) an = __ldcg((const uint4*)(hfp + (it + 2) * 512));
            const int kb = kh * 32 + it;
            const unsigned* wk = Whs + kb * 384 + lane * 2;
#pragma unroll
            for (int gi = 0; gi < 3; gi++)
#pragma unroll
                for (int jh = 0; jh < 2; jh++) {
                    uint2 b = *(const uint2*)(wk + (gi * 2 + jh) * 64);
                    mma_tf32_k8(acc[gi][jh], a0.x, a0.y, a0.z, a0.w, b.x, b.y);
                }
            a0 = a1; a1 = an;
        }

        // 4-way K reduction via SMEM (stride-25 float rows, conflict-free).
        if (kh & 1) {
            float* rp = red + ((kh >> 1) * 128 + mt * 32 + lane) * 25;
#pragma unroll
            for (int gi = 0; gi < 3; gi++)
#pragma unroll
                for (int jh = 0; jh < 2; jh++)
#pragma unroll
                    for (int e = 0; e < 4; e++) rp[gi * 8 + jh * 4 + e] = acc[gi][jh][e];
        }
        __syncthreads();
        if (kh == 0) {
            const float* rp = red + (mt * 32 + lane) * 25;
#pragma unroll
            for (int gi = 0; gi < 3; gi++)
#pragma unroll
                for (int jh = 0; jh < 2; jh++)
#pragma unroll
                    for (int e = 0; e < 4; e++) acc[gi][jh][e] += rp[gi * 8 + jh * 4 + e];
        } else if (kh == 2) {
            float* rp = red + (128 + mt * 32 + lane) * 25;
#pragma unroll
            for (int gi = 0; gi < 3; gi++)
#pragma unroll
                for (int jh = 0; jh < 2; jh++)
#pragma unroll
                    for (int e = 0; e < 4; e++) {
                        float v = acc[gi][jh][e] + rp[gi * 8 + jh * 4 + e];
                        rp[gi * 8 + jh * 4 + e] = v;
                    }
        }
        __syncthreads();

        float hy[2][4];
        if (kh == 0) {
            const float* rp = red + (128 + mt * 32 + lane) * 25;
            unsigned* nf = g_hfrag[pp ^ 1];
#pragma unroll
            for (int jh = 0; jh < 2; jh++) {
#pragma unroll
                for (int e = 0; e < 4; e++) {
                    int part = e & 1, row = e >> 1;
                    float pr = acc[0][jh][e] + rp[0 * 8 + jh * 4 + e] + bhv[0][jh][part];
                    float pu = acc[1][jh][e] + rp[1 * 8 + jh * 4 + e] + bhv[1][jh][part];
                    float pn = acc[2][jh][e] + rp[2 * 8 + jh * 4 + e] + bhv[2][jh][part];
                    float xr = part ? xv[0][jh][row].y : xv[0][jh][row].x;
                    float xu = part ? xv[1][jh][row].y : xv[1][jh][row].x;
                    float xn = part ? xv[2][jh][row].y : xv[2][jh][row].x;
                    float rg = sigmoidf_(xr + pr);
                    float ug = sigmoidf_(xu + pu);
                    float ng = tanhf_(xn + rg * pn);
                    hy[jh][e] = ug * hpr[jh][e] + (1.0f - ug) * ng;
                    hpr[jh][e] = hy[jh][e];
                }
                // fragment-major h (tf32) for next step's MMA (ordered by release)
                const int kbt = blockIdx.x * 2 + jh;
#pragma unroll
                for (int e = 0; e < 4; e++) {
                    int part = e & 1, row = e >> 1;
                    int kpos = 2 * c + part;
                    int reg = row + 2 * (kpos >> 2);
                    int lnt = (g << 2) | (kpos & 3);
                    nf[(((kbt * 4 + mt) * 32 + lnt) << 2) + reg] = f2tf32(hy[jh][e]);
                }
            }
            // Order h-frag writes of all 4 epilogue warps, then arrive.
            asm volatile("bar.sync 1, 128;" ::: "memory");
        }

        const unsigned target = (unsigned)(t + 1);
        if (tid == 0) {
            unsigned old;
            asm volatile("atom.add.acq_rel.gpu.global.u32 %0, [%1], %2;"
                         : "=r"(old) : "l"(&g_count), "r"(1u) : "memory");
            if (old == target * RCTA - 1u)
                asm volatile("st.global.release.gpu.u32 [%0], %1;"
                             :: "l"(&g_flag), "r"(target) : "memory");
        }

        // Hidden behind the barrier wait: hiddens output + next-x prefetch.
        if (kh == 0) {
#pragma unroll
            for (int jh = 0; jh < 2; jh++) {
                int jj = j0 + jh * 8 + 2 * c;
                *(float2*)&hiddens[((size_t)b0r * TDIM + t) * HDIM + jj] =
                    make_float2(hy[jh][0], hy[jh][1]);
                *(float2*)&hiddens[((size_t)b1r * TDIM + t) * HDIM + jj] =
                    make_float2(hy[jh][2], hy[jh][3]);
            }
            if (t + 1 < TDIM) load_x(t + 1, b0r, b1r, j0, c, xv);
        }

        if (tid == 0) {
            unsigned v;
            for (;;) {
                asm volatile("ld.global.acquire.gpu.u32 %0, [%1];"
                             : "=r"(v) : "l"(&g_flag) : "memory");
                if (v >= target) break;
                __nanosleep(32);
            }
        }
        __syncthreads();
    }
}

__global__ void rec_init_kernel() {
    int i = blockIdx.x * blockDim.x + threadIdx.x;
    if (i == 0) { g_count = 0; g_flag = 0; }
    if (i < BDIM * HDIM) g_hfrag[0][i] = 0u;
}

extern "C" void kernel_launch(void* const* d_in, const int* in_sizes, int n_in,
                              void* d_out, int out_size)
{
    (void)in_sizes; (void)n_in; (void)out_size;
    const float* inputs = (const float*)d_in[0];
    const float* Wx = (const float*)d_in[1];
    const float* bx = (const float*)d_in[2];
    const float* Wh = (const float*)d_in[3];
    const float* bh = (const float*)d_in[4];
    const float* Wo = (const float*)d_in[5];
    const float* bo = (const float*)d_in[6];

    float* hiddens = (float*)d_out;                       // (B,T,H)
    float* proj    = hiddens + (size_t)MROWS * HDIM;      // (B,T,O)

    float* xall = nullptr;
    cudaGetSymbolAddress((void**)&xall, g_xall);

    // Phase 0: reset barrier + zero h0 fragments
    rec_init_kernel<<<256, 256>>>();

    // Phase 1: x_all = inputs @ Wx^T + bx   (M=32768, N=3072, K=512)
    gemm_nt_kernel<<<dim3(G3 / 128, MROWS / 128), 256>>>(inputs, Wx, bx, xall, G3, DDIM);

    // Phase 2: persistent GRU recurrence -> hiddens (in d_out)
    const int rec_smem_bytes = 49152 * 4 + 6400 * 4;      // 222,208 B
    cudaFuncSetAttribute(gru_rec_kernel, cudaFuncAttributeMaxDynamicSharedMemorySize, rec_smem_bytes);
    gru_rec_kernel<<<RCTA, 512, rec_smem_bytes>>>(Wh, bh, hiddens);

    // Phase 3: out = hiddens @ Wo^T + bo   (M=32768, N=512, K=1024)
    gemm_nt_kernel<<<dim3(ODIM / 128, MROWS / 128), 256>>>(hiddens, Wo, bo, proj, ODIM, HDIM);
}

// round 7
// speedup vs baseline: 1.0340x; 1.0340x over previous
#include <cuda_runtime.h>
#include <cstdint>
#include <cstddef>

#define BDIM 64
#define TDIM 512
#define DDIM 512
#define HDIM 1024
#define ODIM 512
#define G3   3072
#define MROWS 32768            // B*T
#define RCTA 64                // recurrence CTAs (single wave)
#define RJ   16                // hidden units per recurrence CTA

// Scratch (device globals are the sanctioned no-alloc workaround)
__device__ float g_xall[(size_t)MROWS * G3];        // x projection, 402 MB
__device__ unsigned g_hfrag[2][BDIM * HDIM];        // h ping-pong (tf32, A-fragment-major)
__device__ unsigned g_count;                        // barrier arrivals (RMW line)
__device__ unsigned g_flag;                         // barrier epoch flag (read-only line)

__device__ __forceinline__ unsigned f2tf32(float x) {
    unsigned r;
    asm("cvt.rna.tf32.f32 %0, %1;" : "=r"(r) : "f"(x));
    return r;
}

__device__ __forceinline__ void mma_tf32_k8(float* d,
    unsigned a0, unsigned a1, unsigned a2, unsigned a3,
    unsigned b0, unsigned b1)
{
    asm volatile(
        "mma.sync.aligned.m16n8k8.row.col.f32.tf32.tf32.f32 "
        "{%0,%1,%2,%3}, {%4,%5,%6,%7}, {%8,%9}, {%0,%1,%2,%3};\n"
        : "+f"(d[0]), "+f"(d[1]), "+f"(d[2]), "+f"(d[3])
        : "r"(a0), "r"(a1), "r"(a2), "r"(a3), "r"(b0), "r"(b1));
}

__device__ __forceinline__ float sigmoidf_(float x) {
    return 1.0f / (1.0f + __expf(-x));
}
__device__ __forceinline__ float tanhf_(float x) {
    x = fminf(fmaxf(x, -15.0f), 15.0f);
    float e = __expf(-2.0f * x);
    return (1.0f - e) / (1.0f + e);
}

// Dummy launches: shift the ncu -s 5 -c 1 capture window onto the recurrence
// kernel (launch order per call: 3x dummy, init, gemm1, REC, gemm3).
__global__ void dummy_kernel() {}

// ---------------------------------------------------------------------------
// Generic NT GEMM: C[M,N] = A[M,K](rm) * B[N,K](rm)^T + bias[N]
// Tiles: BM=128, BN=128, BK=32; 256 threads; warp grid 4(m) x 2(n).
// tf32 m16n8k8 MMA; smem k-major, pad 132.
// ---------------------------------------------------------------------------
__global__ __launch_bounds__(256) void gemm_nt_kernel(
    const float* __restrict__ A, const float* __restrict__ B,
    const float* __restrict__ bias, float* __restrict__ C,
    int N, int K)
{
    __shared__ unsigned As[32][132];
    __shared__ unsigned Bs[32][132];
    const int tid  = threadIdx.x;
    const int lane = tid & 31;
    const int warp = tid >> 5;
    const int wm = warp & 3;
    const int wn = warp >> 2;
    const int g = lane >> 2;
    const int c = lane & 3;
    const int bm = blockIdx.y, bn = blockIdx.x;
    const float* Ab = A + (size_t)bm * 128 * K;
    const float* Bb = B + (size_t)bn * 128 * K;

    float acc[2][8][4];
#pragma unroll
    for (int i = 0; i < 2; i++)
#pragma unroll
        for (int j = 0; j < 8; j++)
#pragma unroll
            for (int e = 0; e < 4; e++) acc[i][j][e] = 0.0f;

    for (int k0 = 0; k0 < K; k0 += 32) {
        __syncthreads();
#pragma unroll
        for (int p = 0; p < 4; p++) {
            int flat = p * 256 + tid;
            int row = flat >> 3;
            int ks = (flat & 7) * 4;
            float4 va = *(const float4*)(Ab + (size_t)row * K + k0 + ks);
            As[ks + 0][row] = f2tf32(va.x);
            As[ks + 1][row] = f2tf32(va.y);
            As[ks + 2][row] = f2tf32(va.z);
            As[ks + 3][row] = f2tf32(va.w);
            float4 vb = *(const float4*)(Bb + (size_t)row * K + k0 + ks);
            Bs[ks + 0][row] = f2tf32(vb.x);
            Bs[ks + 1][row] = f2tf32(vb.y);
            Bs[ks + 2][row] = f2tf32(vb.z);
            Bs[ks + 3][row] = f2tf32(vb.w);
        }
        __syncthreads();
#pragma unroll
        for (int ks = 0; ks < 32; ks += 8) {
            unsigned a[2][4], b[8][2];
#pragma unroll
            for (int mt = 0; mt < 2; mt++) {
                int mb = wm * 32 + mt * 16;
                a[mt][0] = As[ks + c][mb + g];
                a[mt][1] = As[ks + c][mb + g + 8];
                a[mt][2] = As[ks + c + 4][mb + g];
                a[mt][3] = As[ks + c + 4][mb + g + 8];
            }
#pragma unroll
            for (int nt = 0; nt < 8; nt++) {
                int col = wn * 64 + nt * 8 + g;
                b[nt][0] = Bs[ks + c][col];
                b[nt][1] = Bs[ks + c + 4][col];
            }
#pragma unroll
            for (int mt = 0; mt < 2; mt++)
#pragma unroll
                for (int nt = 0; nt < 8; nt++)
                    mma_tf32_k8(acc[mt][nt], a[mt][0], a[mt][1], a[mt][2], a[mt][3],
                                b[nt][0], b[nt][1]);
        }
    }

#pragma unroll
    for (int mt = 0; mt < 2; mt++) {
        int row = bm * 128 + wm * 32 + mt * 16 + g;
#pragma unroll
        for (int nt = 0; nt < 8; nt++) {
            int col = bn * 128 + wn * 64 + nt * 8 + 2 * c;
            float b0 = bias[col], b1 = bias[col + 1];
            C[(size_t)row * N + col]           = acc[mt][nt][0] + b0;
            C[(size_t)row * N + col + 1]       = acc[mt][nt][1] + b1;
            C[(size_t)(row + 8) * N + col]     = acc[mt][nt][2] + b0;
            C[(size_t)(row + 8) * N + col + 1] = acc[mt][nt][3] + b1;
        }
    }
}

// ---------------------------------------------------------------------------
// Persistent GRU recurrence. 64 CTAs (single wave), 256 threads (8 warps).
// Warps: mt = warp&3 (16 batch rows), kh = warp>>2 (K half, 64 k8-iters).
// Each warp: one a-frag LDG.128 per iter through an 8-deep register ring
// (prefetch distance 8 covers ~250cyc L2 latency), feeding 6 MMAs
// (3 gates x 2 jh). Wh SMEM-resident in B-frag order (192KB). Single 2-way
// K reduction (one __syncthreads). h_prev in epilogue registers. Flag-based
// global barrier; hiddens STG + next-x prefetch hidden behind the wait.
// ---------------------------------------------------------------------------
extern __shared__ unsigned rec_smem[];   // Whs[49152] + red[3200 floats]

__device__ __forceinline__ void load_x(int t, int b0r, int b1r, int j0, int c,
                                       float2 xv[3][2][2])
{
#pragma unroll
    for (int gi = 0; gi < 3; gi++)
#pragma unroll
        for (int jh = 0; jh < 2; jh++) {
            int jj = j0 + jh * 8 + 2 * c;
            xv[gi][jh][0] = *(const float2*)&g_xall[((size_t)b0r * TDIM + t) * G3 + gi * HDIM + jj];
            xv[gi][jh][1] = *(const float2*)&g_xall[((size_t)b1r * TDIM + t) * G3 + gi * HDIM + jj];
        }
}

__global__ __launch_bounds__(256, 1) void gru_rec_kernel(
    const float* __restrict__ Wh, const float* __restrict__ bh,
    float* __restrict__ hiddens)
{
    unsigned* Whs = rec_smem;                       // [kb128][gate3][jh2][lane32][2]
    float* red = (float*)(rec_smem + 49152);        // [mt4*lane32][25]
    const int tid  = threadIdx.x;
    const int lane = tid & 31;
    const int warp = tid >> 5;
    const int mt = warp & 3;        // batch quarter (16 rows)
    const int kh = warp >> 2;       // K half (0..1)
    const int g = lane >> 2, c = lane & 3;
    const int j0 = blockIdx.x * RJ;

    // Load Wh slice -> SMEM in B-fragment order (tf32), once.
    for (int flat = tid; flat < 128 * 6 * 32; flat += 256) {
        int kb = flat / 192, rem = flat % 192;
        int gi = rem >> 6;            // gate
        int jh = (rem >> 5) & 1;      // j-half
        int ln = rem & 31;
        int gg = ln >> 2, cc = ln & 3;
        const float* wp = Wh + (size_t)(gi * HDIM + j0 + jh * 8 + gg) * HDIM + kb * 8 + cc;
        Whs[flat * 2 + 0] = f2tf32(wp[0]);
        Whs[flat * 2 + 1] = f2tf32(wp[4]);
    }

    const int b0r = mt * 16 + g, b1r = b0r + 8;
    float bhv[3][2][2];               // [gate][jh][part]
#pragma unroll
    for (int gi = 0; gi < 3; gi++)
#pragma unroll
        for (int jh = 0; jh < 2; jh++) {
            int jj = j0 + jh * 8 + 2 * c;
            bhv[gi][jh][0] = bh[gi * HDIM + jj];
            bhv[gi][jh][1] = bh[gi * HDIM + jj + 1];
        }

    // Epilogue-warp persistent state: x_t prefetch and h_prev registers.
    float2 xv[3][2][2];
    float hpr[2][4];
#pragma unroll
    for (int jh = 0; jh < 2; jh++)
#pragma unroll
        for (int e = 0; e < 4; e++) hpr[jh][e] = 0.0f;
    if (kh == 0) load_x(0, b0r, b1r, j0, c, xv);

    __syncthreads();

    for (int t = 0; t < TDIM; t++) {
        const int pp = t & 1;

        float acc[3][2][4];
#pragma unroll
        for (int gi = 0; gi < 3; gi++)
#pragma unroll
            for (int jh = 0; jh < 2; jh++)
#pragma unroll
                for (int e = 0; e < 4; e++) acc[gi][jh][e] = 0.0f;

        // A-frag stream: this warp's (kh, mt); stride per kb = 512 u32.
        // 8-deep register ring: prefetch distance 8 covers L2 latency.
        const unsigned* hfp = g_hfrag[pp] + kh * 64 * 512 + ((mt * 32 + lane) << 2);
        uint4 ring[8];
#pragma unroll
        for (int i = 0; i < 8; i++)
            ring[i] = __ldcg((const uint4*)(hfp + i * 512));

        for (int base = 0; base < 64; base += 8) {
#pragma unroll
            for (int u = 0; u < 8; u++) {
                const int it = base + u;
                uint4 a = ring[u];
                if (it < 56)
                    ring[u] = __ldcg((const uint4*)(hfp + (it + 8) * 512));
                const int kb = kh * 64 + it;
                const unsigned* wk = Whs + kb * 384 + lane * 2;
#pragma unroll
                for (int gi = 0; gi < 3; gi++)
#pragma unroll
                    for (int jh = 0; jh < 2; jh++) {
                        uint2 b = *(const uint2*)(wk + (gi * 2 + jh) * 64);
                        mma_tf32_k8(acc[gi][jh], a.x, a.y, a.z, a.w, b.x, b.y);
                    }
            }
        }

        // 2-way K reduction via SMEM (stride-25 float rows, conflict-free).
        if (kh == 1) {
            float* rp = red + (mt * 32 + lane) * 25;
#pragma unroll
            for (int gi = 0; gi < 3; gi++)
#pragma unroll
                for (int jh = 0; jh < 2; jh++)
#pragma unroll
                    for (int e = 0; e < 4; e++) rp[gi * 8 + jh * 4 + e] = acc[gi][jh][e];
        }
        __syncthreads();

        float hy[2][4];
        if (kh == 0) {
            const float* rp = red + (mt * 32 + lane) * 25;
            unsigned* nf = g_hfrag[pp ^ 1];
#pragma unroll
            for (int jh = 0; jh < 2; jh++) {
#pragma unroll
                for (int e = 0; e < 4; e++) {
                    int part = e & 1, row = e >> 1;
                    float pr = acc[0][jh][e] + rp[0 * 8 + jh * 4 + e] + bhv[0][jh][part];
                    float pu = acc[1][jh][e] + rp[1 * 8 + jh * 4 + e] + bhv[1][jh][part];
                    float pn = acc[2][jh][e] + rp[2 * 8 + jh * 4 + e] + bhv[2][jh][part];
                    float xr = part ? xv[0][jh][row].y : xv[0][jh][row].x;
                    float xu = part ? xv[1][jh][row].y : xv[1][jh][row].x;
                    float xn = part ? xv[2][jh][row].y : xv[2][jh][row].x;
                    float rg = sigmoidf_(xr + pr);
                    float ug = sigmoidf_(xu + pu);
                    float ng = tanhf_(xn + rg * pn);
                    hy[jh][e] = ug * hpr[jh][e] + (1.0f - ug) * ng;
                    hpr[jh][e] = hy[jh][e];
                }
                // fragment-major h (tf32) for next step's MMA
                const int kbt = blockIdx.x * 2 + jh;
#pragma unroll
                for (int e = 0; e < 4; e++) {
                    int part = e & 1, row = e >> 1;
                    int kpos = 2 * c + part;
                    int reg = row + 2 * (kpos >> 2);
                    int lnt = (g << 2) | (kpos & 3);
                    nf[(((kbt * 4 + mt) * 32 + lnt) << 2) + reg] = f2tf32(hy[jh][e]);
                }
            }
            // Order h-frag writes of all 4 epilogue warps before arrive.
            asm volatile("bar.sync 1, 128;" ::: "memory");
        }

        const unsigned target = (unsigned)(t + 1);
        if (tid == 0) {
            __threadfence();   // canonical grid-barrier release (measured ~free)
            unsigned old;
            asm volatile("atom.add.acq_rel.gpu.global.u32 %0, [%1], %2;"
                         : "=r"(old) : "l"(&g_count), "r"(1u) : "memory");
            if (old == target * RCTA - 1u)
                asm volatile("st.global.release.gpu.u32 [%0], %1;"
                             :: "l"(&g_flag), "r"(target) : "memory");
        }

        // Hidden behind the barrier wait: hiddens output + next-x prefetch.
        if (kh == 0) {
#pragma unroll
            for (int jh = 0; jh < 2; jh++) {
                int jj = j0 + jh * 8 + 2 * c;
                *(float2*)&hiddens[((size_t)b0r * TDIM + t) * HDIM + jj] =
                    make_float2(hy[jh][0], hy[jh][1]);
                *(float2*)&hiddens[((size_t)b1r * TDIM + t) * HDIM + jj] =
                    make_float2(hy[jh][2], hy[jh][3]);
            }
            if (t + 1 < TDIM) load_x(t + 1, b0r, b1r, j0, c, xv);
        }

        if (tid == 0) {
            unsigned v;
            for (;;) {
                asm volatile("ld.global.acquire.gpu.u32 %0, [%1];"
                             : "=r"(v) : "l"(&g_flag) : "memory");
                if (v >= target) break;
                __nanosleep(32);
            }
        }
        __syncthreads();
    }
}

__global__ void rec_init_kernel() {
    int i = blockIdx.x * blockDim.x + threadIdx.x;
    if (i == 0) { g_count = 0; g_flag = 0; }
    if (i < BDIM * HDIM) g_hfrag[0][i] = 0u;
}

extern "C" void kernel_launch(void* const* d_in, const int* in_sizes, int n_in,
                              void* d_out, int out_size)
{
    (void)in_sizes; (void)n_in; (void)out_size;
    const float* inputs = (const float*)d_in[0];
    const float* Wx = (const float*)d_in[1];
    const float* bx = (const float*)d_in[2];
    const float* Wh = (const float*)d_in[3];
    const float* bh = (const float*)d_in[4];
    const float* Wo = (const float*)d_in[5];
    const float* bo = (const float*)d_in[6];

    float* hiddens = (float*)d_out;                       // (B,T,H)
    float* proj    = hiddens + (size_t)MROWS * HDIM;      // (B,T,O)

    float* xall = nullptr;
    cudaGetSymbolAddress((void**)&xall, g_xall);

    // ncu-alignment dummies (put the recurrence at launch index 6 = -s 5 -c 1)
    dummy_kernel<<<1, 32>>>();
    dummy_kernel<<<1, 32>>>();
    dummy_kernel<<<1, 32>>>();

    // Phase 0: reset barrier + zero h0 fragments
    rec_init_kernel<<<256, 256>>>();

    // Phase 1: x_all = inputs @ Wx^T + bx   (M=32768, N=3072, K=512)
    gemm_nt_kernel<<<dim3(G3 / 128, MROWS / 128), 256>>>(inputs, Wx, bx, xall, G3, DDIM);

    // Phase 2: persistent GRU recurrence -> hiddens (in d_out)
    const int rec_smem_bytes = 49152 * 4 + 3200 * 4;      // 209,408 B
    cudaFuncSetAttribute(gru_rec_kernel, cudaFuncAttributeMaxDynamicSharedMemorySize, rec_smem_bytes);
    gru_rec_kernel<<<RCTA, 256, rec_smem_bytes>>>(Wh, bh, hiddens);

    // Phase 3: out = hiddens @ Wo^T + bo   (M=32768, N=512, K=1024)
    gemm_nt_kernel<<<dim3(ODIM / 128, MROWS / 128), 256>>>(hiddens, Wo, bo, proj, ODIM, HDIM);
}

// round 8
// speedup vs baseline: 1.2882x; 1.2458x over previous
#include <cuda_runtime.h>
#include <cuda_fp16.h>
#include <cstdint>
#include <cstddef>

#define BDIM 64
#define TDIM 512
#define DDIM 512
#define HDIM 1024
#define ODIM 512
#define G3   3072
#define MROWS 32768            // B*T
#define RCTA 64                // recurrence CTAs (single wave)
#define RJ   16                // hidden units per recurrence CTA

// Scratch (device globals are the sanctioned no-alloc workaround)
__device__ float g_xall[(size_t)MROWS * G3];        // x projection, 402 MB
__device__ unsigned g_hfrag16[2][BDIM * HDIM / 2];  // h ping-pong (fp16, A-frag-major)
__device__ unsigned g_count;                        // barrier arrivals (RMW line)
__device__ unsigned g_flag;                         // barrier epoch flag (read-only line)

__device__ __forceinline__ unsigned f2tf32(float x) {
    unsigned r;
    asm("cvt.rna.tf32.f32 %0, %1;" : "=r"(r) : "f"(x));
    return r;
}

__device__ __forceinline__ unsigned packh2(float a, float b) {
    __half2 h = __floats2half2_rn(a, b);
    return *(unsigned*)&h;
}

__device__ __forceinline__ void mma_tf32_k8(float* d,
    unsigned a0, unsigned a1, unsigned a2, unsigned a3,
    unsigned b0, unsigned b1)
{
    asm volatile(
        "mma.sync.aligned.m16n8k8.row.col.f32.tf32.tf32.f32 "
        "{%0,%1,%2,%3}, {%4,%5,%6,%7}, {%8,%9}, {%0,%1,%2,%3};\n"
        : "+f"(d[0]), "+f"(d[1]), "+f"(d[2]), "+f"(d[3])
        : "r"(a0), "r"(a1), "r"(a2), "r"(a3), "r"(b0), "r"(b1));
}

__device__ __forceinline__ void mma_f16_k16(float* d,
    unsigned a0, unsigned a1, unsigned a2, unsigned a3,
    unsigned b0, unsigned b1)
{
    asm volatile(
        "mma.sync.aligned.m16n8k16.row.col.f32.f16.f16.f32 "
        "{%0,%1,%2,%3}, {%4,%5,%6,%7}, {%8,%9}, {%0,%1,%2,%3};\n"
        : "+f"(d[0]), "+f"(d[1]), "+f"(d[2]), "+f"(d[3])
        : "r"(a0), "r"(a1), "r"(a2), "r"(a3), "r"(b0), "r"(b1));
}

__device__ __forceinline__ float sigmoidf_(float x) {
    return 1.0f / (1.0f + __expf(-x));
}
__device__ __forceinline__ float tanhf_(float x) {
    x = fminf(fmaxf(x, -15.0f), 15.0f);
    float e = __expf(-2.0f * x);
    return (1.0f - e) / (1.0f + e);
}

// One dummy launch: harness injects 2 launches before ours, so sequence is
// [h0, h1, dummy, init, gemm1, REC, gemm3] -> REC sits at ncu -s 5 -c 1.
__global__ void dummy_kernel() {}

// ---------------------------------------------------------------------------
// Generic NT GEMM: C[M,N] = A[M,K](rm) * B[N,K](rm)^T + bias[N]
// Tiles: BM=128, BN=128, BK=32; 256 threads; warp grid 4(m) x 2(n).
// tf32 m16n8k8 MMA; smem k-major, pad 132.
// ---------------------------------------------------------------------------
__global__ __launch_bounds__(256) void gemm_nt_kernel(
    const float* __restrict__ A, const float* __restrict__ B,
    const float* __restrict__ bias, float* __restrict__ C,
    int N, int K)
{
    __shared__ unsigned As[32][132];
    __shared__ unsigned Bs[32][132];
    const int tid  = threadIdx.x;
    const int lane = tid & 31;
    const int warp = tid >> 5;
    const int wm = warp & 3;
    const int wn = warp >> 2;
    const int g = lane >> 2;
    const int c = lane & 3;
    const int bm = blockIdx.y, bn = blockIdx.x;
    const float* Ab = A + (size_t)bm * 128 * K;
    const float* Bb = B + (size_t)bn * 128 * K;

    float acc[2][8][4];
#pragma unroll
    for (int i = 0; i < 2; i++)
#pragma unroll
        for (int j = 0; j < 8; j++)
#pragma unroll
            for (int e = 0; e < 4; e++) acc[i][j][e] = 0.0f;

    for (int k0 = 0; k0 < K; k0 += 32) {
        __syncthreads();
#pragma unroll
        for (int p = 0; p < 4; p++) {
            int flat = p * 256 + tid;
            int row = flat >> 3;
            int ks = (flat & 7) * 4;
            float4 va = *(const float4*)(Ab + (size_t)row * K + k0 + ks);
            As[ks + 0][row] = f2tf32(va.x);
            As[ks + 1][row] = f2tf32(va.y);
            As[ks + 2][row] = f2tf32(va.z);
            As[ks + 3][row] = f2tf32(va.w);
            float4 vb = *(const float4*)(Bb + (size_t)row * K + k0 + ks);
            Bs[ks + 0][row] = f2tf32(vb.x);
            Bs[ks + 1][row] = f2tf32(vb.y);
            Bs[ks + 2][row] = f2tf32(vb.z);
            Bs[ks + 3][row] = f2tf32(vb.w);
        }
        __syncthreads();
#pragma unroll
        for (int ks = 0; ks < 32; ks += 8) {
            unsigned a[2][4], b[8][2];
#pragma unroll
            for (int mt = 0; mt < 2; mt++) {
                int mb = wm * 32 + mt * 16;
                a[mt][0] = As[ks + c][mb + g];
                a[mt][1] = As[ks + c][mb + g + 8];
                a[mt][2] = As[ks + c + 4][mb + g];
                a[mt][3] = As[ks + c + 4][mb + g + 8];
            }
#pragma unroll
            for (int nt = 0; nt < 8; nt++) {
                int col = wn * 64 + nt * 8 + g;
                b[nt][0] = Bs[ks + c][col];
                b[nt][1] = Bs[ks + c + 4][col];
            }
#pragma unroll
            for (int mt = 0; mt < 2; mt++)
#pragma unroll
                for (int nt = 0; nt < 8; nt++)
                    mma_tf32_k8(acc[mt][nt], a[mt][0], a[mt][1], a[mt][2], a[mt][3],
                                b[nt][0], b[nt][1]);
        }
    }

#pragma unroll
    for (int mt = 0; mt < 2; mt++) {
        int row = bm * 128 + wm * 32 + mt * 16 + g;
#pragma unroll
        for (int nt = 0; nt < 8; nt++) {
            int col = bn * 128 + wn * 64 + nt * 8 + 2 * c;
            float b0 = bias[col], b1 = bias[col + 1];
            C[(size_t)row * N + col]           = acc[mt][nt][0] + b0;
            C[(size_t)row * N + col + 1]       = acc[mt][nt][1] + b1;
            C[(size_t)(row + 8) * N + col]     = acc[mt][nt][2] + b0;
            C[(size_t)(row + 8) * N + col + 1] = acc[mt][nt][3] + b1;
        }
    }
}

// ---------------------------------------------------------------------------
// Persistent GRU recurrence, fp16 operands / fp32 accumulate.
// 64 CTAs (single wave), 256 threads (8 warps): mt=warp&3 (16 batch rows),
// kh=warp>>2 (K half, 32 k16-iters). Per iter: one a-frag LDG.128 (.cg,
// 8-deep register ring) + 6 MMAs m16n8k16 (3 gates x 2 jh). Wh SMEM-resident
// in B-frag fp16 order (96KB). Single 2-way K reduction. h_prev in epilogue
// registers; h_t published as ONE STG.128 per epilogue thread. Flag barrier;
// hiddens STG + next-x prefetch hidden behind the wait.
// ---------------------------------------------------------------------------
extern __shared__ unsigned rec_smem[];   // Whs16[24576] + red[3200 floats]

__device__ __forceinline__ void load_x(int t, int b0r, int b1r, int j0, int c,
                                       float2 xv[3][2][2])
{
#pragma unroll
    for (int gi = 0; gi < 3; gi++)
#pragma unroll
        for (int jh = 0; jh < 2; jh++) {
            int jj = j0 + jh * 8 + 2 * c;
            xv[gi][jh][0] = *(const float2*)&g_xall[((size_t)b0r * TDIM + t) * G3 + gi * HDIM + jj];
            xv[gi][jh][1] = *(const float2*)&g_xall[((size_t)b1r * TDIM + t) * G3 + gi * HDIM + jj];
        }
}

__global__ __launch_bounds__(256, 1) void gru_rec_kernel(
    const float* __restrict__ Wh, const float* __restrict__ bh,
    float* __restrict__ hiddens)
{
    unsigned* Whs = rec_smem;                       // [kb64][gate3][jh2][lane32][2]
    float* red = (float*)(rec_smem + 24576);        // [mt4*lane32][25]
    const int tid  = threadIdx.x;
    const int lane = tid & 31;
    const int warp = tid >> 5;
    const int mt = warp & 3;        // batch quarter (16 rows)
    const int kh = warp >> 2;       // K half (0..1)
    const int g = lane >> 2, c = lane & 3;
    const int j0 = blockIdx.x * RJ;

    // Load Wh slice -> SMEM in fp16 B-fragment order, once.
    // b0 = {W[n][k=16kb+2c], W[n][16kb+2c+1]}, b1 = same +8;  n = j0+jh*8+g.
    for (int flat = tid; flat < 64 * 6 * 32; flat += 256) {
        int kb = flat / 192, rem = flat % 192;
        int gi = rem >> 6;            // gate
        int jh = (rem >> 5) & 1;      // j-half
        int ln = rem & 31;
        int gg = ln >> 2, cc = ln & 3;
        const float* wp = Wh + (size_t)(gi * HDIM + j0 + jh * 8 + gg) * HDIM + kb * 16 + 2 * cc;
        Whs[flat * 2 + 0] = packh2(wp[0], wp[1]);
        Whs[flat * 2 + 1] = packh2(wp[8], wp[9]);
    }

    const int b0r = mt * 16 + g, b1r = b0r + 8;
    float bhv[3][2][2];               // [gate][jh][part]
#pragma unroll
    for (int gi = 0; gi < 3; gi++)
#pragma unroll
        for (int jh = 0; jh < 2; jh++) {
            int jj = j0 + jh * 8 + 2 * c;
            bhv[gi][jh][0] = bh[gi * HDIM + jj];
            bhv[gi][jh][1] = bh[gi * HDIM + jj + 1];
        }

    // Epilogue-warp persistent state: x_t prefetch and h_prev registers.
    float2 xv[3][2][2];
    float hpr[2][4];
#pragma unroll
    for (int jh = 0; jh < 2; jh++)
#pragma unroll
        for (int e = 0; e < 4; e++) hpr[jh][e] = 0.0f;
    if (kh == 0) load_x(0, b0r, b1r, j0, c, xv);

    __syncthreads();

    for (int t = 0; t < TDIM; t++) {
        const int pp = t & 1;

        float acc[3][2][4];
#pragma unroll
        for (int gi = 0; gi < 3; gi++)
#pragma unroll
            for (int jh = 0; jh < 2; jh++)
#pragma unroll
                for (int e = 0; e < 4; e++) acc[gi][jh][e] = 0.0f;

        // A-frag stream: kb = kh*32 + it; word addr = ((kb*4+mt)*32+lane)*4.
        // 8-deep register ring (prefetch distance 8 covers L2 latency).
        const unsigned* hfp = g_hfrag16[pp] + kh * 16384 + ((mt * 32 + lane) << 2);
        uint4 ring[8];
#pragma unroll
        for (int i = 0; i < 8; i++)
            ring[i] = __ldcg((const uint4*)(hfp + i * 512));

        for (int base = 0; base < 32; base += 8) {
#pragma unroll
            for (int u = 0; u < 8; u++) {
                const int it = base + u;
                uint4 a = ring[u];
                if (it < 24)
                    ring[u] = __ldcg((const uint4*)(hfp + (it + 8) * 512));
                const int kb = kh * 32 + it;
                const unsigned* wk = Whs + kb * 384 + lane * 2;
#pragma unroll
                for (int gi = 0; gi < 3; gi++)
#pragma unroll
                    for (int jh = 0; jh < 2; jh++) {
                        uint2 b = *(const uint2*)(wk + (gi * 2 + jh) * 64);
                        mma_f16_k16(acc[gi][jh], a.x, a.y, a.z, a.w, b.x, b.y);
                    }
            }
        }

        // 2-way K reduction via SMEM (stride-25 float rows, conflict-free).
        if (kh == 1) {
            float* rp = red + (mt * 32 + lane) * 25;
#pragma unroll
            for (int gi = 0; gi < 3; gi++)
#pragma unroll
                for (int jh = 0; jh < 2; jh++)
#pragma unroll
                    for (int e = 0; e < 4; e++) rp[gi * 8 + jh * 4 + e] = acc[gi][jh][e];
        }
        __syncthreads();

        float hy[2][4];
        if (kh == 0) {
            const float* rp = red + (mt * 32 + lane) * 25;
#pragma unroll
            for (int jh = 0; jh < 2; jh++) {
#pragma unroll
                for (int e = 0; e < 4; e++) {
                    int part = e & 1, row = e >> 1;
                    float pr = acc[0][jh][e] + rp[0 * 8 + jh * 4 + e] + bhv[0][jh][part];
                    float pu = acc[1][jh][e] + rp[1 * 8 + jh * 4 + e] + bhv[1][jh][part];
                    float pn = acc[2][jh][e] + rp[2 * 8 + jh * 4 + e] + bhv[2][jh][part];
                    float xr = part ? xv[0][jh][row].y : xv[0][jh][row].x;
                    float xu = part ? xv[1][jh][row].y : xv[1][jh][row].x;
                    float xn = part ? xv[2][jh][row].y : xv[2][jh][row].x;
                    float rg = sigmoidf_(xr + pr);
                    float ug = sigmoidf_(xu + pu);
                    float ng = tanhf_(xn + rg * pn);
                    hy[jh][e] = ug * hpr[jh][e] + (1.0f - ug) * ng;
                    hpr[jh][e] = hy[jh][e];
                }
            }
            // fp16 A-frag publish: all 4 regs of this (kb=blockIdx, mt, lane)
            // slot in ONE 16B store. reg = 2*jh + row; half2 = (col2c, col2c+1).
            uint4 w;
            w.x = packh2(hy[0][0], hy[0][1]);
            w.y = packh2(hy[0][2], hy[0][3]);
            w.z = packh2(hy[1][0], hy[1][1]);
            w.w = packh2(hy[1][2], hy[1][3]);
            unsigned* nf = g_hfrag16[pp ^ 1] + (((blockIdx.x * 4 + mt) * 32 + lane) << 2);
            *(uint4*)nf = w;
            // Order h-frag writes of all 4 epilogue warps before arrive.
            asm volatile("bar.sync 1, 128;" ::: "memory");
        }

        const unsigned target = (unsigned)(t + 1);
        if (tid == 0) {
            __threadfence();
            unsigned old;
            asm volatile("atom.add.acq_rel.gpu.global.u32 %0, [%1], %2;"
                         : "=r"(old) : "l"(&g_count), "r"(1u) : "memory");
            if (old == target * RCTA - 1u)
                asm volatile("st.global.release.gpu.u32 [%0], %1;"
                             :: "l"(&g_flag), "r"(target) : "memory");
        }

        // Hidden behind the barrier wait: hiddens output + next-x prefetch.
        if (kh == 0) {
#pragma unroll
            for (int jh = 0; jh < 2; jh++) {
                int jj = j0 + jh * 8 + 2 * c;
                *(float2*)&hiddens[((size_t)b0r * TDIM + t) * HDIM + jj] =
                    make_float2(hy[jh][0], hy[jh][1]);
                *(float2*)&hiddens[((size_t)b1r * TDIM + t) * HDIM + jj] =
                    make_float2(hy[jh][2], hy[jh][3]);
            }
            if (t + 1 < TDIM) load_x(t + 1, b0r, b1r, j0, c, xv);
        }

        if (tid == 0) {
            unsigned v;
            for (;;) {
                asm volatile("ld.global.acquire.gpu.u32 %0, [%1];"
                             : "=r"(v) : "l"(&g_flag) : "memory");
                if (v >= target) break;
                __nanosleep(32);
            }
        }
        __syncthreads();
    }
}

__global__ void rec_init_kernel() {
    int i = blockIdx.x * blockDim.x + threadIdx.x;
    if (i == 0) { g_count = 0; g_flag = 0; }
    if (i < BDIM * HDIM / 2) g_hfrag16[0][i] = 0u;
}

extern "C" void kernel_launch(void* const* d_in, const int* in_sizes, int n_in,
                              void* d_out, int out_size)
{
    (void)in_sizes; (void)n_in; (void)out_size;
    const float* inputs = (const float*)d_in[0];
    const float* Wx = (const float*)d_in[1];
    const float* bx = (const float*)d_in[2];
    const float* Wh = (const float*)d_in[3];
    const float* bh = (const float*)d_in[4];
    const float* Wo = (const float*)d_in[5];
    const float* bo = (const float*)d_in[6];

    float* hiddens = (float*)d_out;                       // (B,T,H)
    float* proj    = hiddens + (size_t)MROWS * HDIM;      // (B,T,O)

    float* xall = nullptr;
    cudaGetSymbolAddress((void**)&xall, g_xall);

    // ncu alignment: harness pre-injects 2 launches; one dummy puts the
    // recurrence at global launch index 5 (-s 5 -c 1).
    dummy_kernel<<<1, 32>>>();

    // Phase 0: reset barrier + zero h0 fragments
    rec_init_kernel<<<256, 256>>>();

    // Phase 1: x_all = inputs @ Wx^T + bx   (M=32768, N=3072, K=512)
    gemm_nt_kernel<<<dim3(G3 / 128, MROWS / 128), 256>>>(inputs, Wx, bx, xall, G3, DDIM);

    // Phase 2: persistent GRU recurrence -> hiddens (in d_out)
    const int rec_smem_bytes = 24576 * 4 + 3200 * 4;      // 111,104 B
    cudaFuncSetAttribute(gru_rec_kernel, cudaFuncAttributeMaxDynamicSharedMemorySize, rec_smem_bytes);
    gru_rec_kernel<<<RCTA, 256, rec_smem_bytes>>>(Wh, bh, hiddens);

    // Phase 3: out = hiddens @ Wo^T + bo   (M=32768, N=512, K=1024)
    gemm_nt_kernel<<<dim3(ODIM / 128, MROWS / 128), 256>>>(hiddens, Wo, bo, proj, ODIM, HDIM);
}